// round 12
// baseline (speedup 1.0000x reference)
#include <cuda_runtime.h>
#include <cstdint>

#define BB 64
#define LL 25
#define FF 128
#define PP 10000
#define PT 256        // p-tile per block (2 per thread)
#define NT 128        // threads per k_final block
#define KC 16         // f per W chunk
#define NCH (FF/KC)   // 8 chunks
#define WROW 20       // padded row stride (words) for W chunk (conflict-free)
#define WC_BYTES (2*PT*WROW*4)   // 40960
#define AST 28        // padded l-stride of transposed attn

// ---------------- device scratch ----------------
__device__ float g_q[BB*LL*FF];
__device__ float g_k[BB*LL*FF];
__device__ float g_v[BB*LL*FF];
__device__ float g_attnT[BB*FF*AST];   // transposed attn: [b][f][l(padded 28)]
__device__ float g_ds[BB*LL*LL];
__device__ float g_dt[BB*LL*LL];
__device__ float g_tint[BB*LL];
// 0:ds max 1:ds min 2:dt max 3:dt min 4:is max 5:is min 6:ti max 7:ti min
__device__ int g_stats[8];

__device__ __forceinline__ void redMax(float v, int slot) {
    #pragma unroll
    for (int o = 16; o; o >>= 1) v = fmaxf(v, __shfl_xor_sync(0xffffffffu, v, o));
    if ((threadIdx.x & 31) == 0) atomicMax(&g_stats[slot], __float_as_int(v));
}
__device__ __forceinline__ void redMin(float v, int slot) {
    #pragma unroll
    for (int o = 16; o; o >>= 1) v = fminf(v, __shfl_xor_sync(0xffffffffu, v, o));
    if ((threadIdx.x & 31) == 0) atomicMin(&g_stats[slot], __float_as_int(v));
}

// packed fp32x2 FMA (Blackwell FFMA2, only reachable via PTX)
__device__ __forceinline__ void ffma2(unsigned long long& d, unsigned long long a, unsigned long long b) {
    asm("fma.rn.f32x2 %0, %1, %2, %0;" : "+l"(d) : "l"(a), "l"(b));
}
__device__ __forceinline__ unsigned long long pack2(float x, float y) {
    unsigned long long r; asm("mov.b64 %0, {%1, %2};" : "=l"(r) : "f"(x), "f"(y)); return r;
}
__device__ __forceinline__ float lo2(unsigned long long v) { return __uint_as_float((unsigned)v); }
__device__ __forceinline__ float hi2(unsigned long long v) { return __uint_as_float((unsigned)(v >> 32)); }

// async 16B copy global -> shared (LDGSTS)
__device__ __forceinline__ void cp16(unsigned dst_smem, const void* src) {
    asm volatile("cp.async.cg.shared.global [%0], [%1], 16;\n" :: "r"(dst_smem), "l"(src));
}
__device__ __forceinline__ void cp_commit() {
    asm volatile("cp.async.commit_group;\n");
}
template<int N> __device__ __forceinline__ void cp_wait() {
    asm volatile("cp.async.wait_group %0;\n" :: "n"(N));
}

// ---------------- kernel 0: init reduction slots -------------------------------
__global__ void k_init() {
    int t = threadIdx.x;
    if (t < 8) g_stats[t] = (t & 1) ? 0x7F800000 : 0;
}

// ---------------- kernel 1: embeddings + ds/dt + tint + QKV | dist scan --------
__global__ __launch_bounds__(384) void k_prep_qkv(
        const int* __restrict__ user, const int* __restrict__ poi,
        const int* __restrict__ tod, const int* __restrict__ dow,
        const float* __restrict__ lat, const float* __restrict__ lon,
        const float* __restrict__ ut,
        const float* __restrict__ ue, const float* __restrict__ pe,
        const float* __restrict__ te, const float* __restrict__ de,
        const float* __restrict__ Wq, const float* __restrict__ bq,
        const float* __restrict__ Wk, const float* __restrict__ bk,
        const float* __restrict__ Wv, const float* __restrict__ bv,
        const float* __restrict__ dist) {
    int b = blockIdx.x, tid = threadIdx.x;
    const float INF = __int_as_float(0x7F800000);

    if (blockIdx.y == 1) {
        float mx = 0.f, mn = INF;
        for (int idx = tid; idx < LL*(PP/4); idx += 384) {
            int l = idx / (PP/4), c = idx % (PP/4);
            const float4* d4 = (const float4*)(dist + (size_t)poi[b*LL + l] * PP);
            float4 v = d4[c];
            mx = fmaxf(mx, fmaxf(fmaxf(v.x, v.y), fmaxf(v.z, v.w)));
            mn = fminf(mn, fminf(fminf(v.x, v.y), fminf(v.z, v.w)));
        }
        redMax(mx, 4); redMin(mn, 5);
        return;
    }

    __shared__ __align__(16) float inT[FF*28];

    for (int o = tid; o < LL*FF; o += 384) {
        int l = o >> 7, f = o & 127;
        int base = b*LL + l;
        float v = ue[(size_t)user[base]*FF + f] + pe[(size_t)poi[base]*FF + f]
                + te[tod[base]*FF + f] + de[dow[base]*FF + f];
        inT[f*28 + l] = v;
    }
    for (int o = tid; o < FF*3; o += 384) inT[(o/3)*28 + 25 + (o%3)] = 0.f;

    const float rad = 0.017453292519943295f;
    float mxs = 0.f, mns = INF, mxt = 0.f, mnt = INF;
    for (int e = tid; e < LL*LL; e += 384) {
        int i = e / LL, j = e % LL;
        float la1 = lat[b*LL+i], lo1 = lon[b*LL+i];
        float la2 = lat[b*LL+j], lo2 = lon[b*LL+j];
        float a = 0.5f - 0.5f*cosf((la2-la1)*rad)
                + cosf(la1*rad)*cosf(la2*rad)*(1.0f - cosf((lo2-lo1)*rad))*0.5f;
        float ds = 12742.0f * asinf(sqrtf(a));
        float dt = fabsf(ut[b*LL+i] - ut[b*LL+j]);
        g_ds[b*LL*LL + e] = ds;
        g_dt[b*LL*LL + e] = dt;
        mxs = fmaxf(mxs, ds); mns = fminf(mns, ds);
        mxt = fmaxf(mxt, dt); mnt = fminf(mnt, dt);
    }
    float mxi = 0.f, mni = INF;
    if (tid < LL) {
        float ti = (tid == 0) ? 0.f : fabsf(ut[b*LL+tid] - ut[b*LL+tid-1]);
        g_tint[b*LL + tid] = ti;
        mxi = ti; mni = ti;
    }
    redMax(mxs, 0); redMin(mns, 1);
    redMax(mxt, 2); redMin(mnt, 3);
    redMax(mxi, 6); redMin(mni, 7);
    __syncthreads();

    {
        int m = tid >> 7, f = tid & 127;
        const float* W  = (m == 0) ? Wq : (m == 1) ? Wk : Wv;
        const float* bp = (m == 0) ? bq : (m == 1) ? bk : bv;
        float bias = bp[f];
        unsigned long long acc[13];
        unsigned long long binit = pack2(bias, bias);
        #pragma unroll
        for (int j = 0; j < 13; ++j) acc[j] = binit;

        #pragma unroll 4
        for (int g = 0; g < FF; ++g) {
            float w = W[g*FF + f];
            unsigned long long w2 = pack2(w, w);
            const ulonglong2* row = (const ulonglong2*)(inT + g*28);
            #pragma unroll
            for (int j = 0; j < 6; ++j) {
                ulonglong2 a = row[j];
                ffma2(acc[2*j],   a.x, w2);
                ffma2(acc[2*j+1], a.y, w2);
            }
            unsigned long long a6 = ((const unsigned long long*)(inT + g*28))[12];
            ffma2(acc[12], a6, w2);
        }
        float* dst = ((m == 0) ? g_q : (m == 1) ? g_k : g_v) + (size_t)b*LL*FF;
        #pragma unroll
        for (int j = 0; j < 12; ++j) {
            dst[(2*j)*FF + f]   = lo2(acc[j]);
            dst[(2*j+1)*FF + f] = hi2(acc[j]);
        }
        dst[24*FF + f] = lo2(acc[12]);
    }
}

// ---------------- kernel 2: per-batch attention (emits TRANSPOSED attn) --------
__global__ __launch_bounds__(512) void k_att() {
    int b = blockIdx.x, tid = threadIdx.x;
    __shared__ float qs[LL*FF], ks[LL*FF], vs[LL*FF], aw[LL*LL];
    for (int o = tid; o < LL*(FF/4); o += 512) {
        ((float4*)qs)[o] = ((const float4*)g_q)[(size_t)b*LL*(FF/4) + o];
        ((float4*)ks)[o] = ((const float4*)g_k)[(size_t)b*LL*(FF/4) + o];
        ((float4*)vs)[o] = ((const float4*)g_v)[(size_t)b*LL*(FF/4) + o];
    }
    __syncthreads();
    float su = __int_as_float(g_stats[0]), sl = __int_as_float(g_stats[1]);
    float tu = __int_as_float(g_stats[2]), tl = __int_as_float(g_stats[3]);
    float nis = -1.0f/(su - sl), nit = -1.0f/(tu - tl);
    for (int e = tid; e < LL*LL; e += 512) {
        int i = e / LL, j = e % LL;
        const float4* q4 = (const float4*)(qs + i*FF);
        const float4* k4 = (const float4*)(ks + j*FF);
        float s = 0.f;
        #pragma unroll
        for (int f = 0; f < FF/4; ++f) {
            float4 a = q4[f], c = k4[f];
            s += a.x*c.x + a.y*c.y + a.z*c.z + a.w*c.w;
        }
        float delta = 0.5f*(__expf(g_ds[b*LL*LL + e]*nis) + __expf(g_dt[b*LL*LL + e]*nit));
        aw[e] = s + delta;
    }
    __syncthreads();
    {
        int w = tid >> 5, lane = tid & 31;
        for (int row = w; row < LL; row += 16) {
            float v = (lane < LL) ? aw[row*LL + lane] : -1e30f;
            float m = v;
            #pragma unroll
            for (int o = 16; o; o >>= 1) m = fmaxf(m, __shfl_xor_sync(0xffffffffu, m, o));
            float e = (lane < LL) ? __expf(v - m) : 0.f;
            float s = e;
            #pragma unroll
            for (int o = 16; o; o >>= 1) s += __shfl_xor_sync(0xffffffffu, s, o);
            if (lane < LL) aw[row*LL + lane] = e / s;
        }
    }
    __syncthreads();
    // AV -> transposed output g_attnT[b][f][l], pads zeroed
    float* dstT = g_attnT + (size_t)b*FF*AST;
    for (int o = tid; o < LL*FF; o += 512) {
        int i = o >> 7, f = o & 127;
        float s = 0.f;
        #pragma unroll
        for (int j = 0; j < LL; ++j) s += aw[i*LL + j] * vs[j*FF + f];
        dstT[f*AST + i] = s;
    }
    for (int o = tid; o < FF*3; o += 512) dstT[(o/3)*AST + 25 + (o%3)] = 0.f;
}

// ---------------- kernel 3: fused candidate scoring ----------------------------
// Own-row cp.async: each thread stages and reads ONLY rows tid and tid+NT.
// No barriers in the mainloop; warps free-run.
__global__ __launch_bounds__(NT, 4) void k_final(
        const float* __restrict__ poi_emb, const float* __restrict__ dist,
        const int* __restrict__ poi, const float* __restrict__ w_val,
        const float* __restrict__ b_val, float* __restrict__ out, int out_size) {
    extern __shared__ __align__(16) float Wc[];           // 2 bufs x PT x WROW
    __shared__ __align__(16) float As[FF*AST];            // transposed attn 14.3KB
    __shared__ float sa_s[LL], se_s[LL];
    __shared__ unsigned drow_s[LL];

    int tid = threadIdx.x;
    int b = blockIdx.y;
    int p0 = blockIdx.x * PT;

    int pA = p0 + tid, pB = pA + NT;
    int pcA = min(pA, PP-1), pcB = min(pB, PP-1);
    const float* srcA = poi_emb + (size_t)pcA*FF;
    const float* srcB = poi_emb + (size_t)pcB*FF;

    unsigned wc_base = (unsigned)__cvta_generic_to_shared(Wc);
    unsigned dstA0 = wc_base + (tid*WROW)*4;
    unsigned dstB0 = wc_base + ((tid + NT)*WROW)*4;

    // own-row stage of chunk ch into buffer buf (per-thread, no cross-thread deps)
    auto issue = [&](int ch, int buf) {
        unsigned dA = dstA0 + (unsigned)(buf*PT*WROW*4);
        unsigned dB = dstB0 + (unsigned)(buf*PT*WROW*4);
        const float* sA = srcA + ch*KC;
        const float* sB = srcB + ch*KC;
        #pragma unroll
        for (int seg = 0; seg < 4; ++seg) {
            cp16(dA + seg*16, sA + seg*4);
            cp16(dB + seg*16, sB + seg*4);
        }
        cp_commit();
    };

    issue(0, 0);
    issue(1, 1);

    // stage As + coefficients (single barrier of the kernel)
    for (int o = tid; o < FF*AST/4; o += NT)
        ((float4*)As)[o] = ((const float4*)(g_attnT + (size_t)b*FF*AST))[o];
    if (tid < LL) {
        drow_s[tid] = (unsigned)poi[b*LL + tid];
        float Dt = __int_as_float(g_stats[6]) - __int_as_float(g_stats[7]);
        float s = 0.5f * w_val[tid];
        sa_s[tid] = s;
        se_s[tid] = s * __expf(-g_tint[b*LL + tid] / Dt);
    }
    __syncthreads();

    unsigned long long acc0[13], acc1[13];
    #pragma unroll
    for (int j = 0; j < 13; ++j) { acc0[j] = 0ull; acc1[j] = 0ull; }

    for (int ch = 0; ch < NCH; ++ch) {
        int buf = ch & 1;
        if (ch + 2 < NCH) { cp_wait<1>(); }               // chunk ch arrived (1 group pending)
        else if (ch + 1 < NCH) { cp_wait<1>(); }
        else { cp_wait<0>(); }

        const float* w0 = Wc + (buf*PT + tid)*WROW;
        const float* w1 = Wc + (buf*PT + tid + NT)*WROW;

        float4 wa4_0 = ((const float4*)w0)[0];
        float4 wb4_0 = ((const float4*)w1)[0];
        float4 wa4_1 = ((const float4*)w0)[1];
        float4 wb4_1 = ((const float4*)w1)[1];
        float4 wa4_2 = ((const float4*)w0)[2];
        float4 wb4_2 = ((const float4*)w1)[2];
        float4 wa4_3 = ((const float4*)w0)[3];
        float4 wb4_3 = ((const float4*)w1)[3];

        // refill this buffer with chunk ch+2 (this thread's rows only; reads of
        // chunk ch just completed into registers above)
        if (ch + 2 < NCH) issue(ch + 2, buf);

        float wa_all[KC] = {wa4_0.x, wa4_0.y, wa4_0.z, wa4_0.w,
                            wa4_1.x, wa4_1.y, wa4_1.z, wa4_1.w,
                            wa4_2.x, wa4_2.y, wa4_2.z, wa4_2.w,
                            wa4_3.x, wa4_3.y, wa4_3.z, wa4_3.w};
        float wb_all[KC] = {wb4_0.x, wb4_0.y, wb4_0.z, wb4_0.w,
                            wb4_1.x, wb4_1.y, wb4_1.z, wb4_1.w,
                            wb4_2.x, wb4_2.y, wb4_2.z, wb4_2.w,
                            wb4_3.x, wb4_3.y, wb4_3.z, wb4_3.w};

        #pragma unroll
        for (int ff = 0; ff < KC; ++ff) {
            int f = ch*KC + ff;
            unsigned long long wa2 = pack2(wa_all[ff], wa_all[ff]);
            unsigned long long wb2 = pack2(wb_all[ff], wb_all[ff]);
            const ulonglong2* arow = (const ulonglong2*)(As + f*AST);  // broadcast
            #pragma unroll
            for (int j = 0; j < 6; ++j) {
                ulonglong2 a = arow[j];              // l = 4j..4j+3
                ffma2(acc0[2*j],   a.x, wa2);
                ffma2(acc0[2*j+1], a.y, wa2);
                ffma2(acc1[2*j],   a.x, wb2);
                ffma2(acc1[2*j+1], a.y, wb2);
            }
            unsigned long long a12 = ((const unsigned long long*)(As + f*AST))[12]; // l=24,25
            ffma2(acc0[12], a12, wa2);
            ffma2(acc1[12], a12, wb2);
        }
    }

    // epilogue
    float nis = -1.0f / (__int_as_float(g_stats[4]) - __int_as_float(g_stats[5]));
    float bvv = b_val[0];
    bool dup = (out_size >= 2*BB*PP);

    float preA = bvv, preB = bvv;
    #pragma unroll
    for (int l = 0; l < LL; ++l) {
        const float* drow = dist + (size_t)drow_s[l]*PP;
        float dA = drow[pcA];
        float dB = drow[pcB];
        float sa = sa_s[l], se = se_s[l];
        float g0 = (l & 1) ? hi2(acc0[l>>1]) : lo2(acc0[l>>1]);
        float g1 = (l & 1) ? hi2(acc1[l>>1]) : lo2(acc1[l>>1]);
        preA += (sa * __expf(dA*nis) + se) * g0;
        preB += (sa * __expf(dB*nis) + se) * g1;
    }
    if (pA < PP) {
        int n = b*PP + pA;
        out[n] = preA;
        if (dup) out[BB*PP + n] = preA;
    }
    if (pB < PP) {
        int n = b*PP + pB;
        out[n] = preB;
        if (dup) out[BB*PP + n] = preB;
    }
}

// ---------------- launch ------------------------------------------------------
extern "C" void kernel_launch(void* const* d_in, const int* in_sizes, int n_in,
                              void* d_out, int out_size) {
    const int*   user  = (const int*)d_in[0];
    const int*   poi   = (const int*)d_in[1];
    // d_in[2] = cat (unused)
    const float* lat   = (const float*)d_in[3];
    const float* lon   = (const float*)d_in[4];
    const int*   tod   = (const int*)d_in[5];
    const int*   dow   = (const int*)d_in[6];
    const float* ut    = (const float*)d_in[7];
    const float* ue    = (const float*)d_in[8];
    const float* pe    = (const float*)d_in[9];
    const float* te    = (const float*)d_in[10];
    const float* de    = (const float*)d_in[11];
    const float* Wq    = (const float*)d_in[12];
    const float* bq    = (const float*)d_in[13];
    const float* Wk    = (const float*)d_in[14];
    const float* bk    = (const float*)d_in[15];
    const float* Wv    = (const float*)d_in[16];
    const float* bv    = (const float*)d_in[17];
    const float* w_val = (const float*)d_in[18];
    const float* b_val = (const float*)d_in[19];
    const float* dist  = (const float*)d_in[20];
    float* out = (float*)d_out;

    cudaFuncSetAttribute(k_final, cudaFuncAttributeMaxDynamicSharedMemorySize, WC_BYTES);

    k_init<<<1, 32>>>();
    k_prep_qkv<<<dim3(BB, 2), 384>>>(user, poi, tod, dow, lat, lon, ut, ue, pe, te, de,
                                     Wq, bq, Wk, bk, Wv, bv, dist);
    k_att<<<BB, 512>>>();
    k_final<<<dim3((PP + PT - 1)/PT, BB), NT, WC_BYTES>>>(pe, dist, poi, w_val, b_val, out, out_size);
}

// round 13
// speedup vs baseline: 1.1101x; 1.1101x over previous
#include <cuda_runtime.h>
#include <cstdint>

#define BB 64
#define LL 25
#define FF 128
#define PP 10000
#define PT 256        // p-tile per block (2 per thread)
#define NT 128        // threads per k_final block
#define KC 16         // f per W chunk
#define NCH (FF/KC)   // 8 chunks
#define WROW 20       // padded row stride (words) for W chunk (conflict-free)
#define WC_BYTES (2*PT*WROW*4)   // 40960
#define AST 28        // padded l-stride of transposed attn

// ---------------- device scratch ----------------
__device__ float g_q[BB*LL*FF];
__device__ float g_k[BB*LL*FF];
__device__ float g_v[BB*LL*FF];
__device__ float g_attnT[BB*FF*AST];   // transposed attn: [b][f][l(padded 28)]
__device__ float g_ds[BB*LL*LL];
__device__ float g_dt[BB*LL*LL];
__device__ float g_tint[BB*LL];
// 0:ds max 1:ds min 2:dt max 3:dt min 4:is max 5:is min 6:ti max 7:ti min
__device__ int g_stats[8];

__device__ __forceinline__ void redMax(float v, int slot) {
    #pragma unroll
    for (int o = 16; o; o >>= 1) v = fmaxf(v, __shfl_xor_sync(0xffffffffu, v, o));
    if ((threadIdx.x & 31) == 0) atomicMax(&g_stats[slot], __float_as_int(v));
}
__device__ __forceinline__ void redMin(float v, int slot) {
    #pragma unroll
    for (int o = 16; o; o >>= 1) v = fminf(v, __shfl_xor_sync(0xffffffffu, v, o));
    if ((threadIdx.x & 31) == 0) atomicMin(&g_stats[slot], __float_as_int(v));
}

// packed fp32x2 FMA (Blackwell FFMA2, only reachable via PTX)
__device__ __forceinline__ void ffma2(unsigned long long& d, unsigned long long a, unsigned long long b) {
    asm("fma.rn.f32x2 %0, %1, %2, %0;" : "+l"(d) : "l"(a), "l"(b));
}
__device__ __forceinline__ unsigned long long pack2(float x, float y) {
    unsigned long long r; asm("mov.b64 %0, {%1, %2};" : "=l"(r) : "f"(x), "f"(y)); return r;
}
__device__ __forceinline__ float lo2(unsigned long long v) { return __uint_as_float((unsigned)v); }
__device__ __forceinline__ float hi2(unsigned long long v) { return __uint_as_float((unsigned)(v >> 32)); }

// async 16B copy global -> shared (LDGSTS)
__device__ __forceinline__ void cp16(unsigned dst_smem, const void* src) {
    asm volatile("cp.async.cg.shared.global [%0], [%1], 16;\n" :: "r"(dst_smem), "l"(src));
}
__device__ __forceinline__ void cp_commit() {
    asm volatile("cp.async.commit_group;\n");
}
template<int N> __device__ __forceinline__ void cp_wait() {
    asm volatile("cp.async.wait_group %0;\n" :: "n"(N));
}

// ---------------- kernel 0: init reduction slots -------------------------------
__global__ void k_init() {
    int t = threadIdx.x;
    if (t < 8) g_stats[t] = (t & 1) ? 0x7F800000 : 0;
}

// ---------------- kernel 1: embeddings + ds/dt + tint + QKV | dist scan --------
__global__ __launch_bounds__(384) void k_prep_qkv(
        const int* __restrict__ user, const int* __restrict__ poi,
        const int* __restrict__ tod, const int* __restrict__ dow,
        const float* __restrict__ lat, const float* __restrict__ lon,
        const float* __restrict__ ut,
        const float* __restrict__ ue, const float* __restrict__ pe,
        const float* __restrict__ te, const float* __restrict__ de,
        const float* __restrict__ Wq, const float* __restrict__ bq,
        const float* __restrict__ Wk, const float* __restrict__ bk,
        const float* __restrict__ Wv, const float* __restrict__ bv,
        const float* __restrict__ dist) {
    int b = blockIdx.x, tid = threadIdx.x;
    const float INF = __int_as_float(0x7F800000);

    if (blockIdx.y == 1) {
        float mx = 0.f, mn = INF;
        for (int idx = tid; idx < LL*(PP/4); idx += 384) {
            int l = idx / (PP/4), c = idx % (PP/4);
            const float4* d4 = (const float4*)(dist + (size_t)poi[b*LL + l] * PP);
            float4 v = d4[c];
            mx = fmaxf(mx, fmaxf(fmaxf(v.x, v.y), fmaxf(v.z, v.w)));
            mn = fminf(mn, fminf(fminf(v.x, v.y), fminf(v.z, v.w)));
        }
        redMax(mx, 4); redMin(mn, 5);
        return;
    }

    __shared__ __align__(16) float inT[FF*28];

    for (int o = tid; o < LL*FF; o += 384) {
        int l = o >> 7, f = o & 127;
        int base = b*LL + l;
        float v = ue[(size_t)user[base]*FF + f] + pe[(size_t)poi[base]*FF + f]
                + te[tod[base]*FF + f] + de[dow[base]*FF + f];
        inT[f*28 + l] = v;
    }
    for (int o = tid; o < FF*3; o += 384) inT[(o/3)*28 + 25 + (o%3)] = 0.f;

    const float rad = 0.017453292519943295f;
    float mxs = 0.f, mns = INF, mxt = 0.f, mnt = INF;
    for (int e = tid; e < LL*LL; e += 384) {
        int i = e / LL, j = e % LL;
        float la1 = lat[b*LL+i], lo1 = lon[b*LL+i];
        float la2 = lat[b*LL+j], lo2 = lon[b*LL+j];
        float a = 0.5f - 0.5f*cosf((la2-la1)*rad)
                + cosf(la1*rad)*cosf(la2*rad)*(1.0f - cosf((lo2-lo1)*rad))*0.5f;
        float ds = 12742.0f * asinf(sqrtf(a));
        float dt = fabsf(ut[b*LL+i] - ut[b*LL+j]);
        g_ds[b*LL*LL + e] = ds;
        g_dt[b*LL*LL + e] = dt;
        mxs = fmaxf(mxs, ds); mns = fminf(mns, ds);
        mxt = fmaxf(mxt, dt); mnt = fminf(mnt, dt);
    }
    float mxi = 0.f, mni = INF;
    if (tid < LL) {
        float ti = (tid == 0) ? 0.f : fabsf(ut[b*LL+tid] - ut[b*LL+tid-1]);
        g_tint[b*LL + tid] = ti;
        mxi = ti; mni = ti;
    }
    redMax(mxs, 0); redMin(mns, 1);
    redMax(mxt, 2); redMin(mnt, 3);
    redMax(mxi, 6); redMin(mni, 7);
    __syncthreads();

    {
        int m = tid >> 7, f = tid & 127;
        const float* W  = (m == 0) ? Wq : (m == 1) ? Wk : Wv;
        const float* bp = (m == 0) ? bq : (m == 1) ? bk : bv;
        float bias = bp[f];
        unsigned long long acc[13];
        unsigned long long binit = pack2(bias, bias);
        #pragma unroll
        for (int j = 0; j < 13; ++j) acc[j] = binit;

        #pragma unroll 4
        for (int g = 0; g < FF; ++g) {
            float w = W[g*FF + f];
            unsigned long long w2 = pack2(w, w);
            const ulonglong2* row = (const ulonglong2*)(inT + g*28);
            #pragma unroll
            for (int j = 0; j < 6; ++j) {
                ulonglong2 a = row[j];
                ffma2(acc[2*j],   a.x, w2);
                ffma2(acc[2*j+1], a.y, w2);
            }
            unsigned long long a6 = ((const unsigned long long*)(inT + g*28))[12];
            ffma2(acc[12], a6, w2);
        }
        float* dst = ((m == 0) ? g_q : (m == 1) ? g_k : g_v) + (size_t)b*LL*FF;
        #pragma unroll
        for (int j = 0; j < 12; ++j) {
            dst[(2*j)*FF + f]   = lo2(acc[j]);
            dst[(2*j+1)*FF + f] = hi2(acc[j]);
        }
        dst[24*FF + f] = lo2(acc[12]);
    }
}

// ---------------- kernel 2: per-batch attention (emits TRANSPOSED attn) --------
__global__ __launch_bounds__(512) void k_att() {
    int b = blockIdx.x, tid = threadIdx.x;
    __shared__ float qs[LL*FF], ks[LL*FF], vs[LL*FF], aw[LL*LL];
    for (int o = tid; o < LL*(FF/4); o += 512) {
        ((float4*)qs)[o] = ((const float4*)g_q)[(size_t)b*LL*(FF/4) + o];
        ((float4*)ks)[o] = ((const float4*)g_k)[(size_t)b*LL*(FF/4) + o];
        ((float4*)vs)[o] = ((const float4*)g_v)[(size_t)b*LL*(FF/4) + o];
    }
    __syncthreads();
    float su = __int_as_float(g_stats[0]), sl = __int_as_float(g_stats[1]);
    float tu = __int_as_float(g_stats[2]), tl = __int_as_float(g_stats[3]);
    float nis = -1.0f/(su - sl), nit = -1.0f/(tu - tl);
    for (int e = tid; e < LL*LL; e += 512) {
        int i = e / LL, j = e % LL;
        const float4* q4 = (const float4*)(qs + i*FF);
        const float4* k4 = (const float4*)(ks + j*FF);
        float s = 0.f;
        #pragma unroll
        for (int f = 0; f < FF/4; ++f) {
            float4 a = q4[f], c = k4[f];
            s += a.x*c.x + a.y*c.y + a.z*c.z + a.w*c.w;
        }
        float delta = 0.5f*(__expf(g_ds[b*LL*LL + e]*nis) + __expf(g_dt[b*LL*LL + e]*nit));
        aw[e] = s + delta;
    }
    __syncthreads();
    {
        int w = tid >> 5, lane = tid & 31;
        for (int row = w; row < LL; row += 16) {
            float v = (lane < LL) ? aw[row*LL + lane] : -1e30f;
            float m = v;
            #pragma unroll
            for (int o = 16; o; o >>= 1) m = fmaxf(m, __shfl_xor_sync(0xffffffffu, m, o));
            float e = (lane < LL) ? __expf(v - m) : 0.f;
            float s = e;
            #pragma unroll
            for (int o = 16; o; o >>= 1) s += __shfl_xor_sync(0xffffffffu, s, o);
            if (lane < LL) aw[row*LL + lane] = e / s;
        }
    }
    __syncthreads();
    // AV -> transposed output g_attnT[b][f][l], pads zeroed
    float* dstT = g_attnT + (size_t)b*FF*AST;
    for (int o = tid; o < LL*FF; o += 512) {
        int i = o >> 7, f = o & 127;
        float s = 0.f;
        #pragma unroll
        for (int j = 0; j < LL; ++j) s += aw[i*LL + j] * vs[j*FF + f];
        dstT[f*AST + i] = s;
    }
    for (int o = tid; o < FF*3; o += 512) dstT[(o/3)*AST + 25 + (o%3)] = 0.f;
}

// ---------------- kernel 3: fused candidate scoring ----------------------------
// Cooperative coalesced cp.async staging (R11) + register-resident W (R12):
// the two barriers per chunk bracket only 8 LDS.128; compute runs barrier-free.
__global__ __launch_bounds__(NT, 4) void k_final(
        const float* __restrict__ poi_emb, const float* __restrict__ dist,
        const int* __restrict__ poi, const float* __restrict__ w_val,
        const float* __restrict__ b_val, float* __restrict__ out, int out_size) {
    extern __shared__ __align__(16) float Wc[];           // 2 bufs x PT x WROW
    __shared__ __align__(16) float As[FF*AST];            // transposed attn 14.3KB
    __shared__ float sa_s[LL], se_s[LL];
    __shared__ unsigned drow_s[LL];

    int tid = threadIdx.x;
    int b = blockIdx.y;
    int p0 = blockIdx.x * PT;

    unsigned wc_base = (unsigned)__cvta_generic_to_shared(Wc);
    // cooperative coalesced stage of chunk ch into buffer buf
    auto issue = [&](int ch, int buf) {
        #pragma unroll
        for (int k = 0; k < 8; ++k) {
            int s = k*NT + tid;                          // 0..1023
            int row = s >> 2, seg = s & 3;               // row 0..255
            int prow = min(p0 + row, PP-1);
            const float* src = poi_emb + (size_t)prow*FF + ch*KC + seg*4;
            unsigned dst = wc_base + ((buf*PT + row)*WROW + seg*4)*4;
            cp16(dst, src);
        }
        cp_commit();
    };

    issue(0, 0);
    issue(1, 1);

    // stage As + coefficients
    for (int o = tid; o < FF*AST/4; o += NT)
        ((float4*)As)[o] = ((const float4*)(g_attnT + (size_t)b*FF*AST))[o];
    if (tid < LL) {
        drow_s[tid] = (unsigned)poi[b*LL + tid];
        float Dt = __int_as_float(g_stats[6]) - __int_as_float(g_stats[7]);
        float s = 0.5f * w_val[tid];
        sa_s[tid] = s;
        se_s[tid] = s * __expf(-g_tint[b*LL + tid] / Dt);
    }

    unsigned long long acc0[13], acc1[13];
    #pragma unroll
    for (int j = 0; j < 13; ++j) { acc0[j] = 0ull; acc1[j] = 0ull; }

    for (int ch = 0; ch < NCH; ++ch) {
        int buf = ch & 1;
        if (ch + 1 < NCH) cp_wait<1>(); else cp_wait<0>();
        __syncthreads();                                  // chunk ch visible

        // pull own W rows into registers (8 LDS.128, conflict-free WROW=20)
        const float4* w0 = (const float4*)(Wc + (buf*PT + tid)*WROW);
        const float4* w1 = (const float4*)(Wc + (buf*PT + tid + NT)*WROW);
        float4 wa4_0 = w0[0], wa4_1 = w0[1], wa4_2 = w0[2], wa4_3 = w0[3];
        float4 wb4_0 = w1[0], wb4_1 = w1[1], wb4_2 = w1[2], wb4_3 = w1[3];

        __syncthreads();                                  // all reads done; buf reusable
        if (ch + 2 < NCH) issue(ch + 2, buf);

        float wa_all[KC] = {wa4_0.x, wa4_0.y, wa4_0.z, wa4_0.w,
                            wa4_1.x, wa4_1.y, wa4_1.z, wa4_1.w,
                            wa4_2.x, wa4_2.y, wa4_2.z, wa4_2.w,
                            wa4_3.x, wa4_3.y, wa4_3.z, wa4_3.w};
        float wb_all[KC] = {wb4_0.x, wb4_0.y, wb4_0.z, wb4_0.w,
                            wb4_1.x, wb4_1.y, wb4_1.z, wb4_1.w,
                            wb4_2.x, wb4_2.y, wb4_2.z, wb4_2.w,
                            wb4_3.x, wb4_3.y, wb4_3.z, wb4_3.w};

        #pragma unroll
        for (int ff = 0; ff < KC; ++ff) {
            int f = ch*KC + ff;
            unsigned long long wa2 = pack2(wa_all[ff], wa_all[ff]);
            unsigned long long wb2 = pack2(wb_all[ff], wb_all[ff]);
            const ulonglong2* arow = (const ulonglong2*)(As + f*AST);  // broadcast
            #pragma unroll
            for (int j = 0; j < 6; ++j) {
                ulonglong2 a = arow[j];              // l = 4j..4j+3
                ffma2(acc0[2*j],   a.x, wa2);
                ffma2(acc0[2*j+1], a.y, wa2);
                ffma2(acc1[2*j],   a.x, wb2);
                ffma2(acc1[2*j+1], a.y, wb2);
            }
            unsigned long long a12 = ((const unsigned long long*)(As + f*AST))[12]; // l=24,25
            ffma2(acc0[12], a12, wa2);
            ffma2(acc1[12], a12, wb2);
        }
    }

    // epilogue
    int pA = p0 + tid, pB = pA + NT;
    int pcA = min(pA, PP-1), pcB = min(pB, PP-1);
    float nis = -1.0f / (__int_as_float(g_stats[4]) - __int_as_float(g_stats[5]));
    float bvv = b_val[0];
    bool dup = (out_size >= 2*BB*PP);

    float preA = bvv, preB = bvv;
    #pragma unroll
    for (int l = 0; l < LL; ++l) {
        const float* drow = dist + (size_t)drow_s[l]*PP;
        float dA = drow[pcA];
        float dB = drow[pcB];
        float sa = sa_s[l], se = se_s[l];
        float g0 = (l & 1) ? hi2(acc0[l>>1]) : lo2(acc0[l>>1]);
        float g1 = (l & 1) ? hi2(acc1[l>>1]) : lo2(acc1[l>>1]);
        preA += (sa * __expf(dA*nis) + se) * g0;
        preB += (sa * __expf(dB*nis) + se) * g1;
    }
    if (pA < PP) {
        int n = b*PP + pA;
        out[n] = preA;
        if (dup) out[BB*PP + n] = preA;
    }
    if (pB < PP) {
        int n = b*PP + pB;
        out[n] = preB;
        if (dup) out[BB*PP + n] = preB;
    }
}

// ---------------- launch ------------------------------------------------------
extern "C" void kernel_launch(void* const* d_in, const int* in_sizes, int n_in,
                              void* d_out, int out_size) {
    const int*   user  = (const int*)d_in[0];
    const int*   poi   = (const int*)d_in[1];
    // d_in[2] = cat (unused)
    const float* lat   = (const float*)d_in[3];
    const float* lon   = (const float*)d_in[4];
    const int*   tod   = (const int*)d_in[5];
    const int*   dow   = (const int*)d_in[6];
    const float* ut    = (const float*)d_in[7];
    const float* ue    = (const float*)d_in[8];
    const float* pe    = (const float*)d_in[9];
    const float* te    = (const float*)d_in[10];
    const float* de    = (const float*)d_in[11];
    const float* Wq    = (const float*)d_in[12];
    const float* bq    = (const float*)d_in[13];
    const float* Wk    = (const float*)d_in[14];
    const float* bk    = (const float*)d_in[15];
    const float* Wv    = (const float*)d_in[16];
    const float* bv    = (const float*)d_in[17];
    const float* w_val = (const float*)d_in[18];
    const float* b_val = (const float*)d_in[19];
    const float* dist  = (const float*)d_in[20];
    float* out = (float*)d_out;

    cudaFuncSetAttribute(k_final, cudaFuncAttributeMaxDynamicSharedMemorySize, WC_BYTES);

    k_init<<<1, 32>>>();
    k_prep_qkv<<<dim3(BB, 2), 384>>>(user, poi, tod, dow, lat, lon, ut, ue, pe, te, de,
                                     Wq, bq, Wk, bk, Wv, bv, dist);
    k_att<<<BB, 512>>>();
    k_final<<<dim3((PP + PT - 1)/PT, BB), NT, WC_BYTES>>>(pe, dist, poi, w_val, b_val, out, out_size);
}

// round 14
// speedup vs baseline: 1.1706x; 1.0545x over previous
#include <cuda_runtime.h>
#include <cstdint>

#define BB 64
#define LL 25
#define FF 128
#define PP 10000
#define PT 256        // p-tile per block (2 per thread)
#define NT 128        // threads per k_final block
#define KC 16         // f per W chunk
#define NCH (FF/KC)   // 8 chunks
#define WROW 20       // padded row stride (words) for W chunk (conflict-free)
#define WC_BYTES (2*PT*WROW*4)   // 40960
#define AST 28        // padded l-stride of transposed attn

// ---------------- device scratch ----------------
__device__ float g_v[BB*LL*FF];
__device__ float g_attnT[BB*FF*AST];   // transposed attn: [b][f][l(padded 28)]
__device__ float g_ds[BB*LL*LL];
__device__ float g_dt[BB*LL*LL];
__device__ float g_tint[BB*LL];
__device__ float g_scores[BB*LL*LL];   // q.k scores (no delta)
// per-block partial stats (no init kernel needed)
__device__ float g_pds_max[BB], g_pds_min[BB];   // haversine ds
__device__ float g_pdt_max[BB], g_pdt_min[BB];   // |dt|
__device__ float g_pis_max[BB], g_pis_min[BB];   // dist rows (scan)
__device__ float g_pti_max[BB], g_pti_min[BB];   // time_interval

__device__ __forceinline__ float wredMax(float v) {
    #pragma unroll
    for (int o = 16; o; o >>= 1) v = fmaxf(v, __shfl_xor_sync(0xffffffffu, v, o));
    return v;
}
__device__ __forceinline__ float wredMin(float v) {
    #pragma unroll
    for (int o = 16; o; o >>= 1) v = fminf(v, __shfl_xor_sync(0xffffffffu, v, o));
    return v;
}

// packed fp32x2 FMA (Blackwell FFMA2, only reachable via PTX)
__device__ __forceinline__ void ffma2(unsigned long long& d, unsigned long long a, unsigned long long b) {
    asm("fma.rn.f32x2 %0, %1, %2, %0;" : "+l"(d) : "l"(a), "l"(b));
}
__device__ __forceinline__ unsigned long long pack2(float x, float y) {
    unsigned long long r; asm("mov.b64 %0, {%1, %2};" : "=l"(r) : "f"(x), "f"(y)); return r;
}
__device__ __forceinline__ float lo2(unsigned long long v) { return __uint_as_float((unsigned)v); }
__device__ __forceinline__ float hi2(unsigned long long v) { return __uint_as_float((unsigned)(v >> 32)); }

// async 16B copy global -> shared (LDGSTS)
__device__ __forceinline__ void cp16(unsigned dst_smem, const void* src) {
    asm volatile("cp.async.cg.shared.global [%0], [%1], 16;\n" :: "r"(dst_smem), "l"(src));
}
__device__ __forceinline__ void cp_commit() {
    asm volatile("cp.async.commit_group;\n");
}
template<int N> __device__ __forceinline__ void cp_wait() {
    asm volatile("cp.async.wait_group %0;\n" :: "n"(N));
}

// ---------------- kernel 1: embeds + ds/dt + tint + QKV + QK^T | dist scan -----
__global__ __launch_bounds__(384) void k_prep(
        const int* __restrict__ user, const int* __restrict__ poi,
        const int* __restrict__ tod, const int* __restrict__ dow,
        const float* __restrict__ lat, const float* __restrict__ lon,
        const float* __restrict__ ut,
        const float* __restrict__ ue, const float* __restrict__ pe,
        const float* __restrict__ te, const float* __restrict__ de,
        const float* __restrict__ Wq, const float* __restrict__ bq,
        const float* __restrict__ Wk, const float* __restrict__ bk,
        const float* __restrict__ Wv, const float* __restrict__ bv,
        const float* __restrict__ dist) {
    int b = blockIdx.x, tid = threadIdx.x;
    int wid = tid >> 5, lane = tid & 31;
    const float INF = __int_as_float(0x7F800000);

    if (blockIdx.y == 1) {
        // dist-row max/min scan for this batch's 25 POIs -> per-block partials
        __shared__ float s_mx[12], s_mn[12];
        float mx = 0.f, mn = INF;
        for (int idx = tid; idx < LL*(PP/4); idx += 384) {
            int l = idx / (PP/4), c = idx % (PP/4);
            const float4* d4 = (const float4*)(dist + (size_t)poi[b*LL + l] * PP);
            float4 v = d4[c];
            mx = fmaxf(mx, fmaxf(fmaxf(v.x, v.y), fmaxf(v.z, v.w)));
            mn = fminf(mn, fminf(fminf(v.x, v.y), fminf(v.z, v.w)));
        }
        mx = wredMax(mx); mn = wredMin(mn);
        if (lane == 0) { s_mx[wid] = mx; s_mn[wid] = mn; }
        __syncthreads();
        if (tid == 0) {
            float a = s_mx[0], c = s_mn[0];
            #pragma unroll
            for (int w = 1; w < 12; ++w) { a = fmaxf(a, s_mx[w]); c = fminf(c, s_mn[w]); }
            g_pis_max[b] = a; g_pis_min[b] = c;
        }
        return;
    }

    __shared__ __align__(16) float inT[FF*28];
    __shared__ __align__(16) float qsT[FF*28];
    __shared__ __align__(16) float ksT[FF*28];
    __shared__ float s_red[6][12];

    for (int o = tid; o < LL*FF; o += 384) {
        int l = o >> 7, f = o & 127;
        int base = b*LL + l;
        float v = ue[(size_t)user[base]*FF + f] + pe[(size_t)poi[base]*FF + f]
                + te[tod[base]*FF + f] + de[dow[base]*FF + f];
        inT[f*28 + l] = v;
    }
    for (int o = tid; o < FF*3; o += 384) inT[(o/3)*28 + 25 + (o%3)] = 0.f;

    const float rad = 0.017453292519943295f;
    float mxs = 0.f, mns = INF, mxt = 0.f, mnt = INF;
    for (int e = tid; e < LL*LL; e += 384) {
        int i = e / LL, j = e % LL;
        float la1 = lat[b*LL+i], lo1 = lon[b*LL+i];
        float la2 = lat[b*LL+j], lo2 = lon[b*LL+j];
        float a = 0.5f - 0.5f*cosf((la2-la1)*rad)
                + cosf(la1*rad)*cosf(la2*rad)*(1.0f - cosf((lo2-lo1)*rad))*0.5f;
        float ds = 12742.0f * asinf(sqrtf(a));
        float dt = fabsf(ut[b*LL+i] - ut[b*LL+j]);
        g_ds[b*LL*LL + e] = ds;
        g_dt[b*LL*LL + e] = dt;
        mxs = fmaxf(mxs, ds); mns = fminf(mns, ds);
        mxt = fmaxf(mxt, dt); mnt = fminf(mnt, dt);
    }
    float mxi = 0.f, mni = INF;
    if (tid < LL) {
        float ti = (tid == 0) ? 0.f : fabsf(ut[b*LL+tid] - ut[b*LL+tid-1]);
        g_tint[b*LL + tid] = ti;
        mxi = ti; mni = ti;
    }
    // block-level partial reduction -> per-block global partials
    mxs = wredMax(mxs); mns = wredMin(mns);
    mxt = wredMax(mxt); mnt = wredMin(mnt);
    mxi = wredMax(mxi); mni = wredMin(mni);
    if (lane == 0) {
        s_red[0][wid] = mxs; s_red[1][wid] = mns;
        s_red[2][wid] = mxt; s_red[3][wid] = mnt;
        s_red[4][wid] = mxi; s_red[5][wid] = mni;
    }
    __syncthreads();
    if (tid == 0) {
        float r0 = s_red[0][0], r1 = s_red[1][0], r2 = s_red[2][0];
        float r3 = s_red[3][0], r4 = s_red[4][0], r5 = s_red[5][0];
        #pragma unroll
        for (int w = 1; w < 12; ++w) {
            r0 = fmaxf(r0, s_red[0][w]); r1 = fminf(r1, s_red[1][w]);
            r2 = fmaxf(r2, s_red[2][w]); r3 = fminf(r3, s_red[3][w]);
            r4 = fmaxf(r4, s_red[4][w]); r5 = fminf(r5, s_red[5][w]);
        }
        g_pds_max[b] = r0; g_pds_min[b] = r1;
        g_pdt_max[b] = r2; g_pdt_min[b] = r3;
        g_pti_max[b] = r4; g_pti_min[b] = r5;
    }

    // QKV: thread (m,f); q,k -> smem transposed, v -> global
    {
        int m = tid >> 7, f = tid & 127;
        const float* W  = (m == 0) ? Wq : (m == 1) ? Wk : Wv;
        const float* bp = (m == 0) ? bq : (m == 1) ? bk : bv;
        float bias = bp[f];
        unsigned long long acc[13];
        unsigned long long binit = pack2(bias, bias);
        #pragma unroll
        for (int j = 0; j < 13; ++j) acc[j] = binit;

        #pragma unroll 4
        for (int g = 0; g < FF; ++g) {
            float w = W[g*FF + f];
            unsigned long long w2 = pack2(w, w);
            const ulonglong2* row = (const ulonglong2*)(inT + g*28);
            #pragma unroll
            for (int j = 0; j < 6; ++j) {
                ulonglong2 a = row[j];
                ffma2(acc[2*j],   a.x, w2);
                ffma2(acc[2*j+1], a.y, w2);
            }
            unsigned long long a6 = ((const unsigned long long*)(inT + g*28))[12];
            ffma2(acc[12], a6, w2);
        }
        if (m < 2) {
            float* dT = (m == 0) ? qsT : ksT;
            #pragma unroll
            for (int j = 0; j < 12; ++j) {
                dT[f*28 + 2*j]   = lo2(acc[j]);
                dT[f*28 + 2*j+1] = hi2(acc[j]);
            }
            dT[f*28 + 24] = lo2(acc[12]);
        } else {
            float* dst = g_v + (size_t)b*LL*FF;
            #pragma unroll
            for (int j = 0; j < 12; ++j) {
                dst[(2*j)*FF + f]   = lo2(acc[j]);
                dst[(2*j+1)*FF + f] = hi2(acc[j]);
            }
            dst[24*FF + f] = lo2(acc[12]);
        }
    }
    __syncthreads();

    // QK^T scores (no delta): 625 dots over f
    for (int e = tid; e < LL*LL; e += 384) {
        int i = e / LL, j = e % LL;
        float s = 0.f;
        #pragma unroll 8
        for (int f = 0; f < FF; ++f) s += qsT[f*28 + i] * ksT[f*28 + j];
        g_scores[b*LL*LL + e] = s;
    }
}

// ---------------- kernel 2: delta + softmax + AV (emits transposed attn) -------
__global__ __launch_bounds__(512) void k_att() {
    int b = blockIdx.x, tid = threadIdx.x;
    int wid = tid >> 5, lane = tid & 31;
    __shared__ float vs[LL*FF], aw[LL*LL];
    __shared__ float s_stat[4];

    if (wid < 4) {   // reduce global partial stats: 0 ds_max, 1 ds_min, 2 dt_max, 3 dt_min
        const float* arr = (wid == 0) ? g_pds_max : (wid == 1) ? g_pds_min
                         : (wid == 2) ? g_pdt_max : g_pdt_min;
        float a = arr[lane], c = arr[lane + 32];
        float v = (wid & 1) ? fminf(a, c) : fmaxf(a, c);
        v = (wid & 1) ? wredMin(v) : wredMax(v);
        if (lane == 0) s_stat[wid] = v;
    }
    for (int o = tid; o < LL*(FF/4); o += 512)
        ((float4*)vs)[o] = ((const float4*)g_v)[(size_t)b*LL*(FF/4) + o];
    for (int e = tid; e < LL*LL; e += 512) aw[e] = g_scores[b*LL*LL + e];
    __syncthreads();

    float nis = -1.0f/(s_stat[0] - s_stat[1]), nit = -1.0f/(s_stat[2] - s_stat[3]);
    for (int e = tid; e < LL*LL; e += 512) {
        float delta = 0.5f*(__expf(g_ds[b*LL*LL + e]*nis) + __expf(g_dt[b*LL*LL + e]*nit));
        aw[e] += delta;
    }
    __syncthreads();
    {
        for (int row = wid; row < LL; row += 16) {
            float v = (lane < LL) ? aw[row*LL + lane] : -1e30f;
            float m = wredMax(v);
            float e = (lane < LL) ? __expf(v - m) : 0.f;
            float s = e;
            #pragma unroll
            for (int o = 16; o; o >>= 1) s += __shfl_xor_sync(0xffffffffu, s, o);
            if (lane < LL) aw[row*LL + lane] = e / s;
        }
    }
    __syncthreads();
    float* dstT = g_attnT + (size_t)b*FF*AST;
    for (int o = tid; o < LL*FF; o += 512) {
        int i = o >> 7, f = o & 127;
        float s = 0.f;
        #pragma unroll
        for (int j = 0; j < LL; ++j) s += aw[i*LL + j] * vs[j*FF + f];
        dstT[f*AST + i] = s;
    }
    for (int o = tid; o < FF*3; o += 512) dstT[(o/3)*AST + 25 + (o%3)] = 0.f;
}

// ---------------- kernel 3: fused candidate scoring ----------------------------
__global__ __launch_bounds__(NT, 4) void k_final(
        const float* __restrict__ poi_emb, const float* __restrict__ dist,
        const int* __restrict__ poi, const float* __restrict__ w_val,
        const float* __restrict__ b_val, float* __restrict__ out, int out_size) {
    extern __shared__ __align__(16) float Wc[];           // 2 bufs x PT x WROW
    __shared__ __align__(16) float As[FF*AST];            // transposed attn 14.3KB
    __shared__ float sa_s[LL], se_s[LL];
    __shared__ unsigned drow_s[LL];
    __shared__ float s_stat[4];   // 0 is_max, 1 is_min, 2 ti_max, 3 ti_min

    int tid = threadIdx.x;
    int wid = tid >> 5, lane = tid & 31;
    int b = blockIdx.y;
    int p0 = blockIdx.x * PT;

    unsigned wc_base = (unsigned)__cvta_generic_to_shared(Wc);
    auto issue = [&](int ch, int buf) {
        #pragma unroll
        for (int k = 0; k < 8; ++k) {
            int s = k*NT + tid;
            int row = s >> 2, seg = s & 3;
            int prow = min(p0 + row, PP-1);
            const float* src = poi_emb + (size_t)prow*FF + ch*KC + seg*4;
            unsigned dst = wc_base + ((buf*PT + row)*WROW + seg*4)*4;
            cp16(dst, src);
        }
        cp_commit();
    };

    issue(0, 0);
    issue(1, 1);

    // stats reduce (4 warps, one slot each)
    {
        const float* arr = (wid == 0) ? g_pis_max : (wid == 1) ? g_pis_min
                         : (wid == 2) ? g_pti_max : g_pti_min;
        float a = arr[lane], c = arr[lane + 32];
        float v = (wid & 1) ? fminf(a, c) : fmaxf(a, c);
        v = (wid & 1) ? wredMin(v) : wredMax(v);
        if (lane == 0) s_stat[wid] = v;
    }
    for (int o = tid; o < FF*AST/4; o += NT)
        ((float4*)As)[o] = ((const float4*)(g_attnT + (size_t)b*FF*AST))[o];
    if (tid < LL) drow_s[tid] = (unsigned)poi[b*LL + tid];
    __syncthreads();
    if (tid < LL) {
        float Dt = s_stat[2] - s_stat[3];
        float s = 0.5f * w_val[tid];
        sa_s[tid] = s;
        se_s[tid] = s * __expf(-g_tint[b*LL + tid] / Dt);
    }

    unsigned long long acc0[13], acc1[13];
    #pragma unroll
    for (int j = 0; j < 13; ++j) { acc0[j] = 0ull; acc1[j] = 0ull; }

    for (int ch = 0; ch < NCH; ++ch) {
        int buf = ch & 1;
        if (ch + 1 < NCH) cp_wait<1>(); else cp_wait<0>();
        __syncthreads();

        const float4* w0 = (const float4*)(Wc + (buf*PT + tid)*WROW);
        const float4* w1 = (const float4*)(Wc + (buf*PT + tid + NT)*WROW);
        float4 wa4_0 = w0[0], wa4_1 = w0[1], wa4_2 = w0[2], wa4_3 = w0[3];
        float4 wb4_0 = w1[0], wb4_1 = w1[1], wb4_2 = w1[2], wb4_3 = w1[3];

        __syncthreads();
        if (ch + 2 < NCH) issue(ch + 2, buf);

        float wa_all[KC] = {wa4_0.x, wa4_0.y, wa4_0.z, wa4_0.w,
                            wa4_1.x, wa4_1.y, wa4_1.z, wa4_1.w,
                            wa4_2.x, wa4_2.y, wa4_2.z, wa4_2.w,
                            wa4_3.x, wa4_3.y, wa4_3.z, wa4_3.w};
        float wb_all[KC] = {wb4_0.x, wb4_0.y, wb4_0.z, wb4_0.w,
                            wb4_1.x, wb4_1.y, wb4_1.z, wb4_1.w,
                            wb4_2.x, wb4_2.y, wb4_2.z, wb4_2.w,
                            wb4_3.x, wb4_3.y, wb4_3.z, wb4_3.w};

        #pragma unroll
        for (int ff = 0; ff < KC; ++ff) {
            int f = ch*KC + ff;
            unsigned long long wa2 = pack2(wa_all[ff], wa_all[ff]);
            unsigned long long wb2 = pack2(wb_all[ff], wb_all[ff]);
            const ulonglong2* arow = (const ulonglong2*)(As + f*AST);  // broadcast
            #pragma unroll
            for (int j = 0; j < 6; ++j) {
                ulonglong2 a = arow[j];
                // a.x / a.y adjacent-shared across the two FFMA2 -> operand .reuse
                ffma2(acc0[2*j],   a.x, wa2);
                ffma2(acc1[2*j],   a.x, wb2);
                ffma2(acc0[2*j+1], a.y, wa2);
                ffma2(acc1[2*j+1], a.y, wb2);
            }
            unsigned long long a12 = ((const unsigned long long*)(As + f*AST))[12];
            ffma2(acc0[12], a12, wa2);
            ffma2(acc1[12], a12, wb2);
        }
    }

    // epilogue
    int pA = p0 + tid, pB = pA + NT;
    int pcA = min(pA, PP-1), pcB = min(pB, PP-1);
    float nis = -1.0f / (s_stat[0] - s_stat[1]);
    float bvv = b_val[0];
    bool dup = (out_size >= 2*BB*PP);

    float preA = bvv, preB = bvv;
    #pragma unroll
    for (int l = 0; l < LL; ++l) {
        const float* drow = dist + (size_t)drow_s[l]*PP;
        float dA = drow[pcA];
        float dB = drow[pcB];
        float sa = sa_s[l], se = se_s[l];
        float g0 = (l & 1) ? hi2(acc0[l>>1]) : lo2(acc0[l>>1]);
        float g1 = (l & 1) ? hi2(acc1[l>>1]) : lo2(acc1[l>>1]);
        preA += (sa * __expf(dA*nis) + se) * g0;
        preB += (sa * __expf(dB*nis) + se) * g1;
    }
    if (pA < PP) {
        int n = b*PP + pA;
        out[n] = preA;
        if (dup) out[BB*PP + n] = preA;
    }
    if (pB < PP) {
        int n = b*PP + pB;
        out[n] = preB;
        if (dup) out[BB*PP + n] = preB;
    }
}

// ---------------- launch ------------------------------------------------------
extern "C" void kernel_launch(void* const* d_in, const int* in_sizes, int n_in,
                              void* d_out, int out_size) {
    const int*   user  = (const int*)d_in[0];
    const int*   poi   = (const int*)d_in[1];
    // d_in[2] = cat (unused)
    const float* lat   = (const float*)d_in[3];
    const float* lon   = (const float*)d_in[4];
    const int*   tod   = (const int*)d_in[5];
    const int*   dow   = (const int*)d_in[6];
    const float* ut    = (const float*)d_in[7];
    const float* ue    = (const float*)d_in[8];
    const float* pe    = (const float*)d_in[9];
    const float* te    = (const float*)d_in[10];
    const float* de    = (const float*)d_in[11];
    const float* Wq    = (const float*)d_in[12];
    const float* bq    = (const float*)d_in[13];
    const float* Wk    = (const float*)d_in[14];
    const float* bk    = (const float*)d_in[15];
    const float* Wv    = (const float*)d_in[16];
    const float* bv    = (const float*)d_in[17];
    const float* w_val = (const float*)d_in[18];
    const float* b_val = (const float*)d_in[19];
    const float* dist  = (const float*)d_in[20];
    float* out = (float*)d_out;

    cudaFuncSetAttribute(k_final, cudaFuncAttributeMaxDynamicSharedMemorySize, WC_BYTES);

    k_prep<<<dim3(BB, 2), 384>>>(user, poi, tod, dow, lat, lon, ut, ue, pe, te, de,
                                 Wq, bq, Wk, bk, Wv, bv, dist);
    k_att<<<BB, 512>>>();
    k_final<<<dim3((PP + PT - 1)/PT, BB), NT, WC_BYTES>>>(pe, dist, poi, w_val, b_val, out, out_size);
}

// round 16
// speedup vs baseline: 1.1886x; 1.0154x over previous
#include <cuda_runtime.h>
#include <cstdint>

#define BB 64
#define LL 25
#define FF 128
#define PP 10000
#define PT 256        // p-tile per block (2 per thread)
#define NT 128        // threads per k_final block
#define KC 16         // f per W chunk
#define NCH (FF/KC)   // 8 chunks
#define WROW 20       // padded row stride (words) for W chunk (conflict-free)
#define WC_BYTES (2*PT*WROW*4)   // 40960
#define AST 28        // padded l-stride of transposed attn
#define SB 4          // scan splits per batch

// ---------------- device scratch ----------------
__device__ float g_v[BB*LL*FF];
__device__ float g_attnT[BB*FF*AST];   // transposed attn: [b][f][l(padded 28)]
__device__ float g_ds[BB*LL*LL];
__device__ float g_dt[BB*LL*LL];
__device__ float g_tint[BB*LL];
__device__ float g_scores[BB*LL*LL];   // q.k scores (no delta)
// per-block partial stats (no init kernel needed)
__device__ float g_pds_max[BB], g_pds_min[BB];       // haversine ds
__device__ float g_pdt_max[BB], g_pdt_min[BB];       // |dt|
__device__ float g_pis_max[BB*SB], g_pis_min[BB*SB]; // dist rows (scan, split)
__device__ float g_pti_max[BB], g_pti_min[BB];       // time_interval

__device__ __forceinline__ float wredMax(float v) {
    #pragma unroll
    for (int o = 16; o; o >>= 1) v = fmaxf(v, __shfl_xor_sync(0xffffffffu, v, o));
    return v;
}
__device__ __forceinline__ float wredMin(float v) {
    #pragma unroll
    for (int o = 16; o; o >>= 1) v = fminf(v, __shfl_xor_sync(0xffffffffu, v, o));
    return v;
}

// packed fp32x2 FMA (Blackwell FFMA2, only reachable via PTX)
__device__ __forceinline__ void ffma2(unsigned long long& d, unsigned long long a, unsigned long long b) {
    asm("fma.rn.f32x2 %0, %1, %2, %0;" : "+l"(d) : "l"(a), "l"(b));
}
__device__ __forceinline__ unsigned long long pack2(float x, float y) {
    unsigned long long r; asm("mov.b64 %0, {%1, %2};" : "=l"(r) : "f"(x), "f"(y)); return r;
}
__device__ __forceinline__ float lo2(unsigned long long v) { return __uint_as_float((unsigned)v); }
__device__ __forceinline__ float hi2(unsigned long long v) { return __uint_as_float((unsigned)(v >> 32)); }

// async 16B copy global -> shared (LDGSTS)
__device__ __forceinline__ void cp16(unsigned dst_smem, const void* src) {
    asm volatile("cp.async.cg.shared.global [%0], [%1], 16;\n" :: "r"(dst_smem), "l"(src));
}
__device__ __forceinline__ void cp_commit() {
    asm volatile("cp.async.commit_group;\n");
}
template<int N> __device__ __forceinline__ void cp_wait() {
    asm volatile("cp.async.wait_group %0;\n" :: "n"(N));
}

// ---------------- kernel 1: embeds + ds/dt + tint + QKV + QK^T | dist scan -----
// gridDim.y == 1+SB: y=0 compute; y=1..SB scan part (rows l = part, part+SB, ...)
__global__ __launch_bounds__(384) void k_prep(
        const int* __restrict__ user, const int* __restrict__ poi,
        const int* __restrict__ tod, const int* __restrict__ dow,
        const float* __restrict__ lat, const float* __restrict__ lon,
        const float* __restrict__ ut,
        const float* __restrict__ ue, const float* __restrict__ pe,
        const float* __restrict__ te, const float* __restrict__ de,
        const float* __restrict__ Wq, const float* __restrict__ bq,
        const float* __restrict__ Wk, const float* __restrict__ bk,
        const float* __restrict__ Wv, const float* __restrict__ bv,
        const float* __restrict__ dist) {
    int b = blockIdx.x, tid = threadIdx.x;
    int wid = tid >> 5, lane = tid & 31;
    const float INF = __int_as_float(0x7F800000);

    if (blockIdx.y >= 1) {
        // dist-row max/min scan, rows l = part, part+SB, ...
        int part = blockIdx.y - 1;
        __shared__ float s_mx[12], s_mn[12];
        float mx0 = 0.f, mn0 = INF, mx1 = 0.f, mn1 = INF;
        for (int l = part; l < LL; l += SB) {
            const float4* row = (const float4*)(dist + (size_t)poi[b*LL + l] * PP);
            #pragma unroll 2
            for (int c = tid; c < PP/4; c += 2*384) {
                float4 v = row[c];
                mx0 = fmaxf(mx0, fmaxf(fmaxf(v.x, v.y), fmaxf(v.z, v.w)));
                mn0 = fminf(mn0, fminf(fminf(v.x, v.y), fminf(v.z, v.w)));
                int c2 = c + 384;
                if (c2 < PP/4) {
                    float4 u = row[c2];
                    mx1 = fmaxf(mx1, fmaxf(fmaxf(u.x, u.y), fmaxf(u.z, u.w)));
                    mn1 = fminf(mn1, fminf(fminf(u.x, u.y), fminf(u.z, u.w)));
                }
            }
        }
        float mx = wredMax(fmaxf(mx0, mx1)), mn = wredMin(fminf(mn0, mn1));
        if (lane == 0) { s_mx[wid] = mx; s_mn[wid] = mn; }
        __syncthreads();
        if (tid == 0) {
            float a = s_mx[0], c = s_mn[0];
            #pragma unroll
            for (int w = 1; w < 12; ++w) { a = fmaxf(a, s_mx[w]); c = fminf(c, s_mn[w]); }
            g_pis_max[b*SB + part] = a; g_pis_min[b*SB + part] = c;
        }
        return;
    }

    __shared__ __align__(16) float inT[FF*28];
    __shared__ __align__(16) float qsT[FF*28];
    __shared__ __align__(16) float ksT[FF*28];
    __shared__ float s_red[6][12];

    for (int o = tid; o < LL*FF; o += 384) {
        int l = o >> 7, f = o & 127;
        int base = b*LL + l;
        float v = ue[(size_t)user[base]*FF + f] + pe[(size_t)poi[base]*FF + f]
                + te[tod[base]*FF + f] + de[dow[base]*FF + f];
        inT[f*28 + l] = v;
    }
    for (int o = tid; o < FF*3; o += 384) inT[(o/3)*28 + 25 + (o%3)] = 0.f;

    const float rad = 0.017453292519943295f;
    float mxs = 0.f, mns = INF, mxt = 0.f, mnt = INF;
    for (int e = tid; e < LL*LL; e += 384) {
        int i = e / LL, j = e % LL;
        float la1 = lat[b*LL+i], lo1 = lon[b*LL+i];
        float la2 = lat[b*LL+j], lo2 = lon[b*LL+j];
        float a = 0.5f - 0.5f*cosf((la2-la1)*rad)
                + cosf(la1*rad)*cosf(la2*rad)*(1.0f - cosf((lo2-lo1)*rad))*0.5f;
        float ds = 12742.0f * asinf(sqrtf(a));
        float dt = fabsf(ut[b*LL+i] - ut[b*LL+j]);
        g_ds[b*LL*LL + e] = ds;
        g_dt[b*LL*LL + e] = dt;
        mxs = fmaxf(mxs, ds); mns = fminf(mns, ds);
        mxt = fmaxf(mxt, dt); mnt = fminf(mnt, dt);
    }
    float mxi = 0.f, mni = INF;
    if (tid < LL) {
        float ti = (tid == 0) ? 0.f : fabsf(ut[b*LL+tid] - ut[b*LL+tid-1]);
        g_tint[b*LL + tid] = ti;
        mxi = ti; mni = ti;
    }
    // block-level partial reduction -> per-block global partials
    mxs = wredMax(mxs); mns = wredMin(mns);
    mxt = wredMax(mxt); mnt = wredMin(mnt);
    mxi = wredMax(mxi); mni = wredMin(mni);
    if (lane == 0) {
        s_red[0][wid] = mxs; s_red[1][wid] = mns;
        s_red[2][wid] = mxt; s_red[3][wid] = mnt;
        s_red[4][wid] = mxi; s_red[5][wid] = mni;
    }
    __syncthreads();
    if (tid == 0) {
        float r0 = s_red[0][0], r1 = s_red[1][0], r2 = s_red[2][0];
        float r3 = s_red[3][0], r4 = s_red[4][0], r5 = s_red[5][0];
        #pragma unroll
        for (int w = 1; w < 12; ++w) {
            r0 = fmaxf(r0, s_red[0][w]); r1 = fminf(r1, s_red[1][w]);
            r2 = fmaxf(r2, s_red[2][w]); r3 = fminf(r3, s_red[3][w]);
            r4 = fmaxf(r4, s_red[4][w]); r5 = fminf(r5, s_red[5][w]);
        }
        g_pds_max[b] = r0; g_pds_min[b] = r1;
        g_pdt_max[b] = r2; g_pdt_min[b] = r3;
        g_pti_max[b] = r4; g_pti_min[b] = r5;
    }

    // QKV: thread (m,f); q,k -> smem transposed, v -> global
    {
        int m = tid >> 7, f = tid & 127;
        const float* W  = (m == 0) ? Wq : (m == 1) ? Wk : Wv;
        const float* bp = (m == 0) ? bq : (m == 1) ? bk : bv;
        float bias = bp[f];
        unsigned long long acc[13];
        unsigned long long binit = pack2(bias, bias);
        #pragma unroll
        for (int j = 0; j < 13; ++j) acc[j] = binit;

        #pragma unroll 4
        for (int g = 0; g < FF; ++g) {
            float w = W[g*FF + f];
            unsigned long long w2 = pack2(w, w);
            const ulonglong2* row = (const ulonglong2*)(inT + g*28);
            #pragma unroll
            for (int j = 0; j < 6; ++j) {
                ulonglong2 a = row[j];
                ffma2(acc[2*j],   a.x, w2);
                ffma2(acc[2*j+1], a.y, w2);
            }
            unsigned long long a6 = ((const unsigned long long*)(inT + g*28))[12];
            ffma2(acc[12], a6, w2);
        }
        if (m < 2) {
            float* dT = (m == 0) ? qsT : ksT;
            #pragma unroll
            for (int j = 0; j < 12; ++j) {
                dT[f*28 + 2*j]   = lo2(acc[j]);
                dT[f*28 + 2*j+1] = hi2(acc[j]);
            }
            dT[f*28 + 24] = lo2(acc[12]);
        } else {
            float* dst = g_v + (size_t)b*LL*FF;
            #pragma unroll
            for (int j = 0; j < 12; ++j) {
                dst[(2*j)*FF + f]   = lo2(acc[j]);
                dst[(2*j+1)*FF + f] = hi2(acc[j]);
            }
            dst[24*FF + f] = lo2(acc[12]);
        }
    }
    __syncthreads();

    // QK^T scores (no delta): 625 dots over f
    for (int e = tid; e < LL*LL; e += 384) {
        int i = e / LL, j = e % LL;
        float s = 0.f;
        #pragma unroll 8
        for (int f = 0; f < FF; ++f) s += qsT[f*28 + i] * ksT[f*28 + j];
        g_scores[b*LL*LL + e] = s;
    }
}

// ---------------- kernel 2: delta + softmax + AV (emits transposed attn) -------
__global__ __launch_bounds__(512) void k_att() {
    int b = blockIdx.x, tid = threadIdx.x;
    int wid = tid >> 5, lane = tid & 31;
    __shared__ float vs[LL*FF], aw[LL*LL];
    __shared__ float s_stat[4];

    if (wid < 4) {   // reduce global partial stats: 0 ds_max, 1 ds_min, 2 dt_max, 3 dt_min
        const float* arr = (wid == 0) ? g_pds_max : (wid == 1) ? g_pds_min
                         : (wid == 2) ? g_pdt_max : g_pdt_min;
        float a = arr[lane], c = arr[lane + 32];
        float v = (wid & 1) ? fminf(a, c) : fmaxf(a, c);
        v = (wid & 1) ? wredMin(v) : wredMax(v);
        if (lane == 0) s_stat[wid] = v;
    }
    for (int o = tid; o < LL*(FF/4); o += 512)
        ((float4*)vs)[o] = ((const float4*)g_v)[(size_t)b*LL*(FF/4) + o];
    for (int e = tid; e < LL*LL; e += 512) aw[e] = g_scores[b*LL*LL + e];
    __syncthreads();

    float nis = -1.0f/(s_stat[0] - s_stat[1]), nit = -1.0f/(s_stat[2] - s_stat[3]);
    for (int e = tid; e < LL*LL; e += 512) {
        float delta = 0.5f*(__expf(g_ds[b*LL*LL + e]*nis) + __expf(g_dt[b*LL*LL + e]*nit));
        aw[e] += delta;
    }
    __syncthreads();
    {
        for (int row = wid; row < LL; row += 16) {
            float v = (lane < LL) ? aw[row*LL + lane] : -1e30f;
            float m = wredMax(v);
            float e = (lane < LL) ? __expf(v - m) : 0.f;
            float s = e;
            #pragma unroll
            for (int o = 16; o; o >>= 1) s += __shfl_xor_sync(0xffffffffu, s, o);
            if (lane < LL) aw[row*LL + lane] = e / s;
        }
    }
    __syncthreads();
    float* dstT = g_attnT + (size_t)b*FF*AST;
    for (int o = tid; o < LL*FF; o += 512) {
        int i = o >> 7, f = o & 127;
        float s = 0.f;
        #pragma unroll
        for (int j = 0; j < LL; ++j) s += aw[i*LL + j] * vs[j*FF + f];
        dstT[f*AST + i] = s;
    }
    for (int o = tid; o < FF*3; o += 512) dstT[(o/3)*AST + 25 + (o%3)] = 0.f;
}

// ---------------- kernel 3: fused candidate scoring ----------------------------
__global__ __launch_bounds__(NT, 4) void k_final(
        const float* __restrict__ poi_emb, const float* __restrict__ dist,
        const int* __restrict__ poi, const float* __restrict__ w_val,
        const float* __restrict__ b_val, float* __restrict__ out, int out_size) {
    extern __shared__ __align__(16) float Wc[];           // 2 bufs x PT x WROW
    __shared__ __align__(16) float As[FF*AST];            // transposed attn 14.3KB
    __shared__ float sa_s[LL], se_s[LL];
    __shared__ unsigned drow_s[LL];
    __shared__ float s_stat[4];   // 0 is_max, 1 is_min, 2 ti_max, 3 ti_min

    int tid = threadIdx.x;
    int wid = tid >> 5, lane = tid & 31;
    int b = blockIdx.y;
    int p0 = blockIdx.x * PT;

    unsigned wc_base = (unsigned)__cvta_generic_to_shared(Wc);
    auto issue = [&](int ch, int buf) {
        #pragma unroll
        for (int k = 0; k < 8; ++k) {
            int s = k*NT + tid;
            int row = s >> 2, seg = s & 3;
            int prow = min(p0 + row, PP-1);
            const float* src = poi_emb + (size_t)prow*FF + ch*KC + seg*4;
            unsigned dst = wc_base + ((buf*PT + row)*WROW + seg*4)*4;
            cp16(dst, src);
        }
        cp_commit();
    };

    issue(0, 0);
    issue(1, 1);

    // stats reduce: warps 0/1 reduce the BB*SB scan partials; warps 2/3 the BB tint partials
    {
        if (wid < 2) {
            const float* arr = (wid == 0) ? g_pis_max : g_pis_min;
            float v = arr[lane];
            #pragma unroll
            for (int k = 1; k < BB*SB/32; ++k) {
                float x = arr[lane + 32*k];
                v = (wid & 1) ? fminf(v, x) : fmaxf(v, x);
            }
            v = (wid & 1) ? wredMin(v) : wredMax(v);
            if (lane == 0) s_stat[wid] = v;
        } else {
            const float* arr = (wid == 2) ? g_pti_max : g_pti_min;
            float a = arr[lane], c = arr[lane + 32];
            float v = (wid & 1) ? fminf(a, c) : fmaxf(a, c);
            v = (wid & 1) ? wredMin(v) : wredMax(v);
            if (lane == 0) s_stat[wid] = v;
        }
    }
    for (int o = tid; o < FF*AST/4; o += NT)
        ((float4*)As)[o] = ((const float4*)(g_attnT + (size_t)b*FF*AST))[o];
    if (tid < LL) drow_s[tid] = (unsigned)poi[b*LL + tid];
    __syncthreads();
    if (tid < LL) {
        float Dt = s_stat[2] - s_stat[3];
        float s = 0.5f * w_val[tid];
        sa_s[tid] = s;
        se_s[tid] = s * __expf(-g_tint[b*LL + tid] / Dt);
    }

    unsigned long long acc0[13], acc1[13];
    #pragma unroll
    for (int j = 0; j < 13; ++j) { acc0[j] = 0ull; acc1[j] = 0ull; }

    for (int ch = 0; ch < NCH; ++ch) {
        int buf = ch & 1;
        if (ch + 1 < NCH) cp_wait<1>(); else cp_wait<0>();
        __syncthreads();

        const float4* w0 = (const float4*)(Wc + (buf*PT + tid)*WROW);
        const float4* w1 = (const float4*)(Wc + (buf*PT + tid + NT)*WROW);
        float4 wa4_0 = w0[0], wa4_1 = w0[1], wa4_2 = w0[2], wa4_3 = w0[3];
        float4 wb4_0 = w1[0], wb4_1 = w1[1], wb4_2 = w1[2], wb4_3 = w1[3];

        __syncthreads();
        if (ch + 2 < NCH) issue(ch + 2, buf);

        float wa_all[KC] = {wa4_0.x, wa4_0.y, wa4_0.z, wa4_0.w,
                            wa4_1.x, wa4_1.y, wa4_1.z, wa4_1.w,
                            wa4_2.x, wa4_2.y, wa4_2.z, wa4_2.w,
                            wa4_3.x, wa4_3.y, wa4_3.z, wa4_3.w};
        float wb_all[KC] = {wb4_0.x, wb4_0.y, wb4_0.z, wb4_0.w,
                            wb4_1.x, wb4_1.y, wb4_1.z, wb4_1.w,
                            wb4_2.x, wb4_2.y, wb4_2.z, wb4_2.w,
                            wb4_3.x, wb4_3.y, wb4_3.z, wb4_3.w};

        #pragma unroll
        for (int ff = 0; ff < KC; ++ff) {
            int f = ch*KC + ff;
            unsigned long long wa2 = pack2(wa_all[ff], wa_all[ff]);
            unsigned long long wb2 = pack2(wb_all[ff], wb_all[ff]);
            const ulonglong2* arow = (const ulonglong2*)(As + f*AST);  // broadcast
            #pragma unroll
            for (int j = 0; j < 6; ++j) {
                ulonglong2 a = arow[j];
                // a.x / a.y adjacent-shared across the two FFMA2 -> operand .reuse
                ffma2(acc0[2*j],   a.x, wa2);
                ffma2(acc1[2*j],   a.x, wb2);
                ffma2(acc0[2*j+1], a.y, wa2);
                ffma2(acc1[2*j+1], a.y, wb2);
            }
            unsigned long long a12 = ((const unsigned long long*)(As + f*AST))[12];
            ffma2(acc0[12], a12, wa2);
            ffma2(acc1[12], a12, wb2);
        }
    }

    // epilogue
    int pA = p0 + tid, pB = pA + NT;
    int pcA = min(pA, PP-1), pcB = min(pB, PP-1);
    float nis = -1.0f / (s_stat[0] - s_stat[1]);
    float bvv = b_val[0];
    bool dup = (out_size >= 2*BB*PP);

    float preA = bvv, preB = bvv;
    #pragma unroll
    for (int l = 0; l < LL; ++l) {
        const float* drow = dist + (size_t)drow_s[l]*PP;
        float dA = drow[pcA];
        float dB = drow[pcB];
        float sa = sa_s[l], se = se_s[l];
        float g0 = (l & 1) ? hi2(acc0[l>>1]) : lo2(acc0[l>>1]);
        float g1 = (l & 1) ? hi2(acc1[l>>1]) : lo2(acc1[l>>1]);
        preA += (sa * __expf(dA*nis) + se) * g0;
        preB += (sa * __expf(dB*nis) + se) * g1;
    }
    if (pA < PP) {
        int n = b*PP + pA;
        out[n] = preA;
        if (dup) out[BB*PP + n] = preA;
    }
    if (pB < PP) {
        int n = b*PP + pB;
        out[n] = preB;
        if (dup) out[BB*PP + n] = preB;
    }
}

// ---------------- launch ------------------------------------------------------
extern "C" void kernel_launch(void* const* d_in, const int* in_sizes, int n_in,
                              void* d_out, int out_size) {
    const int*   user  = (const int*)d_in[0];
    const int*   poi   = (const int*)d_in[1];
    // d_in[2] = cat (unused)
    const float* lat   = (const float*)d_in[3];
    const float* lon   = (const float*)d_in[4];
    const int*   tod   = (const int*)d_in[5];
    const int*   dow   = (const int*)d_in[6];
    const float* ut    = (const float*)d_in[7];
    const float* ue    = (const float*)d_in[8];
    const float* pe    = (const float*)d_in[9];
    const float* te    = (const float*)d_in[10];
    const float* de    = (const float*)d_in[11];
    const float* Wq    = (const float*)d_in[12];
    const float* bq    = (const float*)d_in[13];
    const float* Wk    = (const float*)d_in[14];
    const float* bk    = (const float*)d_in[15];
    const float* Wv    = (const float*)d_in[16];
    const float* bv    = (const float*)d_in[17];
    const float* w_val = (const float*)d_in[18];
    const float* b_val = (const float*)d_in[19];
    const float* dist  = (const float*)d_in[20];
    float* out = (float*)d_out;

    cudaFuncSetAttribute(k_final, cudaFuncAttributeMaxDynamicSharedMemorySize, WC_BYTES);

    k_prep<<<dim3(BB, 1 + SB), 384>>>(user, poi, tod, dow, lat, lon, ut, ue, pe, te, de,
                                      Wq, bq, Wk, bk, Wv, bv, dist);
    k_att<<<BB, 512>>>();
    k_final<<<dim3((PP + PT - 1)/PT, BB), NT, WC_BYTES>>>(pe, dist, poi, w_val, b_val, out, out_size);
}